// round 10
// baseline (speedup 1.0000x reference)
#include <cuda_runtime.h>
#include <cuda_bf16.h>
#include <math.h>
#include <stdint.h>

#define NNODES 50000
#define NEDGES 800000
#define HC 128
#define NHEADS 8
#define NEG_SLOPE 0.2f
#define LN_EPS 1e-5f
#define SCAN_NBLK ((NNODES + 1023) / 1024)
#define GEMM_TM 128
#define GEMM_NBLK ((NNODES + GEMM_TM - 1) / GEMM_TM)
#define PIT 132

// ---------------- scratch ----------------
__device__ float g_h[NNODES * HC];
__device__ float g_asrc[NNODES * NHEADS];
__device__ float g_adst[NNODES * NHEADS];
__device__ float g_coefA[NHEADS];
__device__ float g_coefB[NHEADS];
__device__ int   g_rowstart[NNODES + 1];
__device__ int   g_cursor[NNODES + 1];
__device__ int   g_srcs[NEDGES];
__device__ float g_eav[NEDGES];
__device__ int   g_bsum[SCAN_NBLK];
__device__ int   g_bsumscan[SCAN_NBLK];
__device__ __nv_bfloat16 g_Wh[HC * HC];
__device__ __nv_bfloat16 g_Wl[HC * HC];

// k-permutation for mma fragment loads
__host__ __device__ __forceinline__ int pk(int k) {
    int b = k & 15;
    return (k & ~15) + (((b & 7) >> 1) << 2) + (((b >> 3) & 1) << 1) + (b & 1);
}

__device__ __forceinline__ void mma_bf16(float c[4], uint32_t a0, uint32_t a1,
                                         uint32_t a2, uint32_t a3,
                                         uint32_t b0, uint32_t b1) {
    asm volatile(
        "mma.sync.aligned.m16n8k16.row.col.f32.bf16.bf16.f32 "
        "{%0,%1,%2,%3}, {%4,%5,%6,%7}, {%8,%9}, {%0,%1,%2,%3};"
        : "+f"(c[0]), "+f"(c[1]), "+f"(c[2]), "+f"(c[3])
        : "r"(a0), "r"(a1), "r"(a2), "r"(a3), "r"(b0), "r"(b1));
}

// ---------------- K: W^T -> bf16 hi/lo, k-permuted ----------------
__global__ void k_prepW(const float* __restrict__ W) {
    int i = blockIdx.x * blockDim.x + threadIdx.x;
    if (i >= HC * HC) return;
    int k = i >> 7, n = i & 127;
    float w = W[i];
    __nv_bfloat16 hi = __float2bfloat16_rn(w);
    __nv_bfloat16 lo = __float2bfloat16_rn(w - __bfloat162float(hi));
    int off = n * HC + pk(k);
    g_Wh[off] = hi;
    g_Wl[off] = lo;
}

// ---------------- K0: edge-MLP collapse ----------------
__global__ void k_coef(const float* __restrict__ lw, const float* __restrict__ lb,
                       const float* __restrict__ ae) {
    int t = threadIdx.x;
    int h = t >> 4, c = t & 15;
    float a  = ae[t];
    float pA = lw[t] * a;
    float pB = lb[t] * a;
    #pragma unroll
    for (int o = 8; o >= 1; o >>= 1) {
        pA += __shfl_xor_sync(0xffffffffu, pA, o);
        pB += __shfl_xor_sync(0xffffffffu, pB, o);
    }
    if (c == 0) { g_coefA[h] = pA; g_coefB[h] = pB; }
}

// ---------------- CSR build ----------------
__global__ void k_zero() {
    int i = blockIdx.x * blockDim.x + threadIdx.x;
    if (i <= NNODES) g_rowstart[i] = 0;
}
// 4-wide count: int4 loads, 4x MLP per thread
__global__ void k_count(const int4* __restrict__ dst4) {
    int e = blockIdx.x * blockDim.x + threadIdx.x;
    if (e < NEDGES / 4) {
        int4 d = dst4[e];
        atomicAdd(&g_rowstart[d.x + 1], 1);
        atomicAdd(&g_rowstart[d.y + 1], 1);
        atomicAdd(&g_rowstart[d.z + 1], 1);
        atomicAdd(&g_rowstart[d.w + 1], 1);
    }
}
__global__ void k_scanA() {
    __shared__ int ws[32];
    int t = threadIdx.x, lane = t & 31, w = t >> 5;
    int idx = 1 + blockIdx.x * 1024 + t;
    int v = (idx <= NNODES) ? g_rowstart[idx] : 0;
    int xv = v;
    #pragma unroll
    for (int o = 1; o < 32; o <<= 1) {
        int y = __shfl_up_sync(0xffffffffu, xv, o);
        if (lane >= o) xv += y;
    }
    if (lane == 31) ws[w] = xv;
    __syncthreads();
    if (w == 0) {
        int s = ws[lane];
        #pragma unroll
        for (int o = 1; o < 32; o <<= 1) {
            int y = __shfl_up_sync(0xffffffffu, s, o);
            if (lane >= o) s += y;
        }
        ws[lane] = s;
    }
    __syncthreads();
    int incl = xv + (w > 0 ? ws[w - 1] : 0);
    if (idx <= NNODES) g_rowstart[idx] = incl;
    if (t == 1023) g_bsum[blockIdx.x] = incl;
}
__global__ void k_scanB() {
    __shared__ int ws[2];
    int t = threadIdx.x, lane = t & 31, w = t >> 5;
    int v = (t < SCAN_NBLK) ? g_bsum[t] : 0;
    #pragma unroll
    for (int o = 1; o < 32; o <<= 1) {
        int y = __shfl_up_sync(0xffffffffu, v, o);
        if (lane >= o) v += y;
    }
    if (lane == 31) ws[w] = v;
    __syncthreads();
    if (w == 1) v += ws[0];
    if (t < SCAN_NBLK) g_bsumscan[t] = v;
}
__global__ void k_scanC() {
    int t = threadIdx.x;
    int idx = 1 + blockIdx.x * 1024 + t;
    if (blockIdx.x == 0 && t == 0) { g_rowstart[0] = 0; g_cursor[0] = 0; }
    if (idx <= NNODES) {
        int off = (blockIdx.x > 0) ? g_bsumscan[blockIdx.x - 1] : 0;
        int v = g_rowstart[idx] + off;
        g_rowstart[idx] = v;
        g_cursor[idx] = v;
    }
}
// 4-wide scatter
__global__ void k_scatter(const int4* __restrict__ src4, const int4* __restrict__ dst4,
                          const float4* __restrict__ ea4) {
    int e = blockIdx.x * blockDim.x + threadIdx.x;
    if (e < NEDGES / 4) {
        int4 s = src4[e];
        int4 d = dst4[e];
        float4 a = ea4[e];
        int p0 = atomicAdd(&g_cursor[d.x], 1);
        int p1 = atomicAdd(&g_cursor[d.y], 1);
        int p2 = atomicAdd(&g_cursor[d.z], 1);
        int p3 = atomicAdd(&g_cursor[d.w], 1);
        g_srcs[p0] = s.x; g_eav[p0] = a.x;
        g_srcs[p1] = s.y; g_eav[p1] = a.y;
        g_srcs[p2] = s.z; g_eav[p2] = a.z;
        g_srcs[p3] = s.w; g_eav[p3] = a.w;
    }
}

// ---------------- mma.sync GEMM (validated R9) ----------------
__global__ __launch_bounds__(256)
void k_gemm_mma(const float* __restrict__ x, const float* __restrict__ att_src,
                const float* __restrict__ att_dst) {
    extern __shared__ char sm[];
    uint16_t* xsh = (uint16_t*)sm;
    uint16_t* xsl = xsh + HC * PIT;
    uint16_t* wsh = xsl + HC * PIT;
    uint16_t* wsl = wsh + HC * PIT;
    float* s_as = (float*)(wsl + HC * PIT);
    float* s_ad = s_as + HC;

    int tid = threadIdx.x;
    int row0 = blockIdx.x * GEMM_TM;

    if (tid < HC) { s_as[tid] = att_src[tid]; s_ad[tid] = att_dst[tid]; }

    {
        const uint32_t* sh = (const uint32_t*)g_Wh;
        const uint32_t* sl = (const uint32_t*)g_Wl;
        #pragma unroll
        for (int jj = 0; jj < 32; jj++) {
            int j = tid + 256 * jj;
            int n = j >> 6, e2 = j & 63;
            *(uint32_t*)&wsh[n * PIT + e2 * 2] = sh[j];
            *(uint32_t*)&wsl[n * PIT + e2 * 2] = sl[j];
        }
    }

    #pragma unroll
    for (int it = 0; it < 16; it++) {
        int i = tid + 256 * it;
        int row = i >> 5;
        int k4 = (i & 31) << 2;
        int gr = row0 + row;
        float4 v = make_float4(0.f, 0.f, 0.f, 0.f);
        if (gr < NNODES) v = *(const float4*)&x[gr * HC + k4];
        __nv_bfloat16 h0 = __float2bfloat16_rn(v.x);
        __nv_bfloat16 h1 = __float2bfloat16_rn(v.y);
        __nv_bfloat16 h2 = __float2bfloat16_rn(v.z);
        __nv_bfloat16 h3 = __float2bfloat16_rn(v.w);
        __nv_bfloat16 l0 = __float2bfloat16_rn(v.x - __bfloat162float(h0));
        __nv_bfloat16 l1 = __float2bfloat16_rn(v.y - __bfloat162float(h1));
        __nv_bfloat16 l2 = __float2bfloat16_rn(v.z - __bfloat162float(h2));
        __nv_bfloat16 l3 = __float2bfloat16_rn(v.w - __bfloat162float(h3));
        uint32_t ph0 = (uint32_t)__bfloat16_as_ushort(h0) | ((uint32_t)__bfloat16_as_ushort(h1) << 16);
        uint32_t ph1 = (uint32_t)__bfloat16_as_ushort(h2) | ((uint32_t)__bfloat16_as_ushort(h3) << 16);
        uint32_t pl0 = (uint32_t)__bfloat16_as_ushort(l0) | ((uint32_t)__bfloat16_as_ushort(l1) << 16);
        uint32_t pl1 = (uint32_t)__bfloat16_as_ushort(l2) | ((uint32_t)__bfloat16_as_ushort(l3) << 16);
        int p = pk(k4);
        *(uint32_t*)&xsh[row * PIT + p] = ph0;
        *(uint32_t*)&xsh[row * PIT + p + 4] = ph1;
        *(uint32_t*)&xsl[row * PIT + p] = pl0;
        *(uint32_t*)&xsl[row * PIT + p + 4] = pl1;
    }
    __syncthreads();

    int w = tid >> 5, lane = tid & 31;
    int g = lane >> 2, t = lane & 3;
    int r0 = w * 16;

    float c[16][4];
    #pragma unroll
    for (int nt = 0; nt < 16; nt++)
        { c[nt][0] = 0.f; c[nt][1] = 0.f; c[nt][2] = 0.f; c[nt][3] = 0.f; }

    for (int k0 = 0; k0 < HC; k0 += 16) {
        int ab = k0 + 4 * t;
        uint2 ah0 = *(const uint2*)&xsh[(r0 + g) * PIT + ab];
        uint2 ah1 = *(const uint2*)&xsh[(r0 + g + 8) * PIT + ab];
        uint2 al0 = *(const uint2*)&xsl[(r0 + g) * PIT + ab];
        uint2 al1 = *(const uint2*)&xsl[(r0 + g + 8) * PIT + ab];
        #pragma unroll
        for (int nt = 0; nt < 16; nt++) {
            int n = nt * 8 + g;
            uint2 bh = *(const uint2*)&wsh[n * PIT + ab];
            uint2 bl = *(const uint2*)&wsl[n * PIT + ab];
            mma_bf16(c[nt], ah0.x, ah1.x, ah0.y, ah1.y, bh.x, bh.y);
            mma_bf16(c[nt], ah0.x, ah1.x, ah0.y, ah1.y, bl.x, bl.y);
            mma_bf16(c[nt], al0.x, al1.x, al0.y, al1.y, bh.x, bh.y);
        }
    }

    int gr0 = row0 + r0 + g;
    int gr1 = gr0 + 8;
    float as0[NHEADS], ad0[NHEADS], as1[NHEADS], ad1[NHEADS];
    #pragma unroll
    for (int hh = 0; hh < NHEADS; hh++)
        { as0[hh] = 0.f; ad0[hh] = 0.f; as1[hh] = 0.f; ad1[hh] = 0.f; }

    #pragma unroll
    for (int nt = 0; nt < 16; nt++) {
        int col = nt * 8 + t * 2;
        int hh = nt >> 1;
        float a0 = s_as[col], a1 = s_as[col + 1];
        float d0 = s_ad[col], d1 = s_ad[col + 1];
        as0[hh] += c[nt][0] * a0 + c[nt][1] * a1;
        ad0[hh] += c[nt][0] * d0 + c[nt][1] * d1;
        as1[hh] += c[nt][2] * a0 + c[nt][3] * a1;
        ad1[hh] += c[nt][2] * d0 + c[nt][3] * d1;
        if (gr0 < NNODES)
            *(float2*)&g_h[gr0 * HC + col] = make_float2(c[nt][0], c[nt][1]);
        if (gr1 < NNODES)
            *(float2*)&g_h[gr1 * HC + col] = make_float2(c[nt][2], c[nt][3]);
    }
    #pragma unroll
    for (int hh = 0; hh < NHEADS; hh++) {
        #pragma unroll
        for (int o = 1; o <= 2; o <<= 1) {
            as0[hh] += __shfl_xor_sync(0xffffffffu, as0[hh], o);
            ad0[hh] += __shfl_xor_sync(0xffffffffu, ad0[hh], o);
            as1[hh] += __shfl_xor_sync(0xffffffffu, as1[hh], o);
            ad1[hh] += __shfl_xor_sync(0xffffffffu, ad1[hh], o);
        }
    }
    if (t == 0) {
        #pragma unroll
        for (int hh = 0; hh < NHEADS; hh++) {
            if (gr0 < NNODES) {
                g_asrc[gr0 * NHEADS + hh] = as0[hh];
                g_adst[gr0 * NHEADS + hh] = ad0[hh];
            }
            if (gr1 < NNODES) {
                g_asrc[gr1 * NHEADS + hh] = as1[hh];
                g_adst[gr1 * NHEADS + hh] = ad1[hh];
            }
        }
    }
}

// ---------------- fused softmax + aggregate + residual + LN + ELU (4-wide ILP) ---------
__global__ void k_agg(const float* __restrict__ x, const float* __restrict__ b,
                      const float* __restrict__ gamma, const float* __restrict__ beta,
                      float* __restrict__ out) {
    int gw = (blockIdx.x * blockDim.x + threadIdx.x) >> 5;
    if (gw >= NNODES) return;
    int n = gw;
    int lane = threadIdx.x & 31;
    int cb = lane * 4;
    int head = lane >> 2;

    int beg = g_rowstart[n];
    int end = g_rowstart[n + 1];
    float adst2 = g_adst[n * NHEADS + head] + g_coefB[head];
    float cA = g_coefA[head];

    float4 acc0 = make_float4(0.f, 0.f, 0.f, 0.f);
    float4 acc1 = make_float4(0.f, 0.f, 0.f, 0.f);
    float4 acc2 = make_float4(0.f, 0.f, 0.f, 0.f);
    float4 acc3 = make_float4(0.f, 0.f, 0.f, 0.f);
    float sum0 = 0.f, sum1 = 0.f, sum2 = 0.f, sum3 = 0.f;

    for (int base = beg; base < end; base += 32) {
        int i = base + lane;
        int sj = 0; float aj = 0.f;
        if (i < end) { sj = g_srcs[i]; aj = g_eav[i]; }
        int m = end - base; if (m > 32) m = 32;
        int tt = 0;
        for (; tt + 3 < m; tt += 4) {
            int   s0 = __shfl_sync(0xffffffffu, sj, tt);
            int   s1 = __shfl_sync(0xffffffffu, sj, tt + 1);
            int   s2 = __shfl_sync(0xffffffffu, sj, tt + 2);
            int   s3 = __shfl_sync(0xffffffffu, sj, tt + 3);
            float a0 = __shfl_sync(0xffffffffu, aj, tt);
            float a1 = __shfl_sync(0xffffffffu, aj, tt + 1);
            float a2 = __shfl_sync(0xffffffffu, aj, tt + 2);
            float a3 = __shfl_sync(0xffffffffu, aj, tt + 3);
            float g0 = g_asrc[s0 * NHEADS + head];
            float g1 = g_asrc[s1 * NHEADS + head];
            float g2 = g_asrc[s2 * NHEADS + head];
            float g3 = g_asrc[s3 * NHEADS + head];
            float4 h0 = *(const float4*)&g_h[s0 * HC + cb];
            float4 h1 = *(const float4*)&g_h[s1 * HC + cb];
            float4 h2 = *(const float4*)&g_h[s2 * HC + cb];
            float4 h3 = *(const float4*)&g_h[s3 * HC + cb];
            float l0 = fmaf(a0, cA, g0 + adst2);
            float l1 = fmaf(a1, cA, g1 + adst2);
            float l2 = fmaf(a2, cA, g2 + adst2);
            float l3 = fmaf(a3, cA, g3 + adst2);
            l0 = l0 > 0.f ? l0 : NEG_SLOPE * l0;
            l1 = l1 > 0.f ? l1 : NEG_SLOPE * l1;
            l2 = l2 > 0.f ? l2 : NEG_SLOPE * l2;
            l3 = l3 > 0.f ? l3 : NEG_SLOPE * l3;
            float e0 = __expf(l0);
            float e1 = __expf(l1);
            float e2 = __expf(l2);
            float e3 = __expf(l3);
            sum0 += e0; sum1 += e1; sum2 += e2; sum3 += e3;
            acc0.x += e0 * h0.x; acc0.y += e0 * h0.y; acc0.z += e0 * h0.z; acc0.w += e0 * h0.w;
            acc1.x += e1 * h1.x; acc1.y += e1 * h1.y; acc1.z += e1 * h1.z; acc1.w += e1 * h1.w;
            acc2.x += e2 * h2.x; acc2.y += e2 * h2.y; acc2.z += e2 * h2.z; acc2.w += e2 * h2.w;
            acc3.x += e3 * h3.x; acc3.y += e3 * h3.y; acc3.z += e3 * h3.z; acc3.w += e3 * h3.w;
        }
        for (; tt < m; ++tt) {
            int   s0 = __shfl_sync(0xffffffffu, sj, tt);
            float a0 = __shfl_sync(0xffffffffu, aj, tt);
            float l0 = fmaf(a0, cA, g_asrc[s0 * NHEADS + head] + adst2);
            l0 = l0 > 0.f ? l0 : NEG_SLOPE * l0;
            float e0 = __expf(l0);
            float4 h0 = *(const float4*)&g_h[s0 * HC + cb];
            sum0 += e0;
            acc0.x += e0 * h0.x; acc0.y += e0 * h0.y; acc0.z += e0 * h0.z; acc0.w += e0 * h0.w;
        }
    }
    float sum = (sum0 + sum1) + (sum2 + sum3);
    float4 acc;
    acc.x = (acc0.x + acc1.x) + (acc2.x + acc3.x);
    acc.y = (acc0.y + acc1.y) + (acc2.y + acc3.y);
    acc.z = (acc0.z + acc1.z) + (acc2.z + acc3.z);
    acc.w = (acc0.w + acc1.w) + (acc2.w + acc3.w);

    float inv = 1.f / (sum + 1e-16f);
    float4 xv = *(const float4*)&x[n * HC + cb];
    float4 bv = *(const float4*)&b[cb];
    float4 o;
    o.x = acc.x * inv + bv.x + xv.x;
    o.y = acc.y * inv + bv.y + xv.y;
    o.z = acc.z * inv + bv.z + xv.z;
    o.w = acc.w * inv + bv.w + xv.w;

    float s1 = o.x + o.y + o.z + o.w;
    float s2 = o.x * o.x + o.y * o.y + o.z * o.z + o.w * o.w;
    #pragma unroll
    for (int off = 16; off >= 1; off >>= 1) {
        s1 += __shfl_xor_sync(0xffffffffu, s1, off);
        s2 += __shfl_xor_sync(0xffffffffu, s2, off);
    }
    float mu = s1 * (1.f / 128.f);
    float var = s2 * (1.f / 128.f) - mu * mu;
    float rstd = rsqrtf(var + LN_EPS);
    float4 g4 = *(const float4*)&gamma[cb];
    float4 be4 = *(const float4*)&beta[cb];
    o.x = (o.x - mu) * rstd * g4.x + be4.x;
    o.y = (o.y - mu) * rstd * g4.y + be4.y;
    o.z = (o.z - mu) * rstd * g4.z + be4.z;
    o.w = (o.w - mu) * rstd * g4.w + be4.w;
    o.x = o.x > 0.f ? o.x : expm1f(o.x);
    o.y = o.y > 0.f ? o.y : expm1f(o.y);
    o.z = o.z > 0.f ? o.z : expm1f(o.z);
    o.w = o.w > 0.f ? o.w : expm1f(o.w);

    *(float4*)&out[n * HC + cb] = o;
}

// ---------------- launch ----------------
extern "C" void kernel_launch(void* const* d_in, const int* in_sizes, int n_in,
                              void* d_out, int out_size) {
    const float* x        = (const float*)d_in[0];
    const int*   ei       = (const int*)d_in[1];
    const float* ea       = (const float*)d_in[2];
    const float* W        = (const float*)d_in[3];
    const float* b        = (const float*)d_in[4];
    const float* att_src  = (const float*)d_in[5];
    const float* att_dst  = (const float*)d_in[6];
    const float* att_edge = (const float*)d_in[7];
    const float* lw       = (const float*)d_in[8];
    const float* lb       = (const float*)d_in[9];
    const float* gamma    = (const float*)d_in[10];
    const float* beta     = (const float*)d_in[11];
    const int4* src4 = (const int4*)ei;
    const int4* dst4 = (const int4*)(ei + NEDGES);
    const float4* ea4 = (const float4*)ea;
    float* out = (float*)d_out;

    const int smem_sz = 4 * HC * PIT * (int)sizeof(uint16_t) + 2 * HC * (int)sizeof(float);
    cudaFuncSetAttribute(k_gemm_mma, cudaFuncAttributeMaxDynamicSharedMemorySize, smem_sz);

    k_coef<<<1, 128>>>(lw, lb, att_edge);
    k_prepW<<<(HC * HC + 255) / 256, 256>>>(W);
    k_zero<<<(NNODES + 1 + 255) / 256, 256>>>();
    k_count<<<(NEDGES / 4 + 255) / 256, 256>>>(dst4);
    k_gemm_mma<<<GEMM_NBLK, 256, smem_sz>>>(x, att_src, att_dst);
    k_scanA<<<SCAN_NBLK, 1024>>>();
    k_scanB<<<1, 64>>>();
    k_scanC<<<SCAN_NBLK, 1024>>>();
    k_scatter<<<(NEDGES / 4 + 255) / 256, 256>>>(src4, dst4, ea4);
    k_agg<<<(NNODES * 32 + 255) / 256, 256>>>(x, b, gamma, beta, out);
}

// round 11
// speedup vs baseline: 1.1273x; 1.1273x over previous
#include <cuda_runtime.h>
#include <cuda_bf16.h>
#include <math.h>
#include <stdint.h>

#define NNODES 50000
#define NEDGES 800000
#define HC 128
#define NHEADS 8
#define NEG_SLOPE 0.2f
#define LN_EPS 1e-5f
#define SCAN_NBLK ((NNODES + 1023) / 1024)
#define GEMM_TM 128
#define GEMM_NBLK ((NNODES + GEMM_TM - 1) / GEMM_TM)
#define PIT 132
#define ZERO_NBLK ((NNODES + 1 + 255) / 256)

// ---------------- scratch ----------------
__device__ float g_h[NNODES * HC];
__device__ float g_asrc[NNODES * NHEADS];
__device__ float g_adst[NNODES * NHEADS];
__device__ float g_coefA[NHEADS];
__device__ float g_coefB[NHEADS];
__device__ int   g_rowstart[NNODES + 1];
__device__ int   g_cursor[NNODES + 1];
__device__ long long g_edge[NEDGES];      // packed (eav<<32 | src), sorted by dst
__device__ int   g_bsum[SCAN_NBLK];
__device__ int   g_bsumscan[SCAN_NBLK];
__device__ __nv_bfloat16 g_Wh[HC * HC];
__device__ __nv_bfloat16 g_Wl[HC * HC];

// k-permutation for mma fragment loads
__host__ __device__ __forceinline__ int pk(int k) {
    int b = k & 15;
    return (k & ~15) + (((b & 7) >> 1) << 2) + (((b >> 3) & 1) << 1) + (b & 1);
}

__device__ __forceinline__ void mma_bf16(float c[4], uint32_t a0, uint32_t a1,
                                         uint32_t a2, uint32_t a3,
                                         uint32_t b0, uint32_t b1) {
    asm volatile(
        "mma.sync.aligned.m16n8k16.row.col.f32.bf16.bf16.f32 "
        "{%0,%1,%2,%3}, {%4,%5,%6,%7}, {%8,%9}, {%0,%1,%2,%3};"
        : "+f"(c[0]), "+f"(c[1]), "+f"(c[2]), "+f"(c[3])
        : "r"(a0), "r"(a1), "r"(a2), "r"(a3), "r"(b0), "r"(b1));
}

// ---------------- fused prep: W split/permute + coef + rowstart zero ----------------
__global__ void k_prep(const float* __restrict__ W, const float* __restrict__ lw,
                       const float* __restrict__ lb, const float* __restrict__ ae) {
    int bx = blockIdx.x, t = threadIdx.x;
    if (bx < 64) {                         // W: 16384 elems
        int i = bx * 256 + t;
        int k = i >> 7, n = i & 127;
        float w = W[i];
        __nv_bfloat16 hi = __float2bfloat16_rn(w);
        __nv_bfloat16 lo = __float2bfloat16_rn(w - __bfloat162float(hi));
        int off = n * HC + pk(k);
        g_Wh[off] = hi;
        g_Wl[off] = lo;
    } else if (bx == 64) {                 // edge-MLP collapse
        if (t < 128) {
            int h = t >> 4, c = t & 15;
            float a  = ae[t];
            float pA = lw[t] * a;
            float pB = lb[t] * a;
            #pragma unroll
            for (int o = 8; o >= 1; o >>= 1) {
                pA += __shfl_xor_sync(0xffffffffu, pA, o);
                pB += __shfl_xor_sync(0xffffffffu, pB, o);
            }
            if (c == 0) { g_coefA[h] = pA; g_coefB[h] = pB; }
        }
    } else {                               // zero rowstart
        int i = (bx - 65) * 256 + t;
        if (i <= NNODES) g_rowstart[i] = 0;
    }
}

// ---------------- CSR build ----------------
__global__ void k_count(const int* __restrict__ dst) {
    int e = blockIdx.x * blockDim.x + threadIdx.x;
    if (e < NEDGES) atomicAdd(&g_rowstart[dst[e] + 1], 1);
}
__global__ void k_scanA() {
    __shared__ int ws[32];
    int t = threadIdx.x, lane = t & 31, w = t >> 5;
    int idx = 1 + blockIdx.x * 1024 + t;
    int v = (idx <= NNODES) ? g_rowstart[idx] : 0;
    int xv = v;
    #pragma unroll
    for (int o = 1; o < 32; o <<= 1) {
        int y = __shfl_up_sync(0xffffffffu, xv, o);
        if (lane >= o) xv += y;
    }
    if (lane == 31) ws[w] = xv;
    __syncthreads();
    if (w == 0) {
        int s = ws[lane];
        #pragma unroll
        for (int o = 1; o < 32; o <<= 1) {
            int y = __shfl_up_sync(0xffffffffu, s, o);
            if (lane >= o) s += y;
        }
        ws[lane] = s;
    }
    __syncthreads();
    int incl = xv + (w > 0 ? ws[w - 1] : 0);
    if (idx <= NNODES) g_rowstart[idx] = incl;
    if (t == 1023) g_bsum[blockIdx.x] = incl;
}
__global__ void k_scanB() {
    __shared__ int ws[2];
    int t = threadIdx.x, lane = t & 31, w = t >> 5;
    int v = (t < SCAN_NBLK) ? g_bsum[t] : 0;
    #pragma unroll
    for (int o = 1; o < 32; o <<= 1) {
        int y = __shfl_up_sync(0xffffffffu, v, o);
        if (lane >= o) v += y;
    }
    if (lane == 31) ws[w] = v;
    __syncthreads();
    if (w == 1) v += ws[0];
    if (t < SCAN_NBLK) g_bsumscan[t] = v;
}
__global__ void k_scanC() {
    int t = threadIdx.x;
    int idx = 1 + blockIdx.x * 1024 + t;
    if (blockIdx.x == 0 && t == 0) { g_rowstart[0] = 0; g_cursor[0] = 0; }
    if (idx <= NNODES) {
        int off = (blockIdx.x > 0) ? g_bsumscan[blockIdx.x - 1] : 0;
        int v = g_rowstart[idx] + off;
        g_rowstart[idx] = v;
        g_cursor[idx] = v;
    }
}
__global__ void k_scatter(const int* __restrict__ src, const int* __restrict__ dst,
                          const float* __restrict__ ea) {
    int e = blockIdx.x * blockDim.x + threadIdx.x;
    if (e < NEDGES) {
        int d = dst[e];
        int pos = atomicAdd(&g_cursor[d], 1);
        long long p = ((long long)__float_as_int(ea[e]) << 32) | (unsigned)src[e];
        g_edge[pos] = p;
    }
}

// ---------------- mma.sync GEMM (validated R9) ----------------
__global__ __launch_bounds__(256)
void k_gemm_mma(const float* __restrict__ x, const float* __restrict__ att_src,
                const float* __restrict__ att_dst) {
    extern __shared__ char sm[];
    uint16_t* xsh = (uint16_t*)sm;
    uint16_t* xsl = xsh + HC * PIT;
    uint16_t* wsh = xsl + HC * PIT;
    uint16_t* wsl = wsh + HC * PIT;
    float* s_as = (float*)(wsl + HC * PIT);
    float* s_ad = s_as + HC;

    int tid = threadIdx.x;
    int row0 = blockIdx.x * GEMM_TM;

    if (tid < HC) { s_as[tid] = att_src[tid]; s_ad[tid] = att_dst[tid]; }

    {
        const uint32_t* sh = (const uint32_t*)g_Wh;
        const uint32_t* sl = (const uint32_t*)g_Wl;
        #pragma unroll
        for (int jj = 0; jj < 32; jj++) {
            int j = tid + 256 * jj;
            int n = j >> 6, e2 = j & 63;
            *(uint32_t*)&wsh[n * PIT + e2 * 2] = sh[j];
            *(uint32_t*)&wsl[n * PIT + e2 * 2] = sl[j];
        }
    }

    #pragma unroll
    for (int it = 0; it < 16; it++) {
        int i = tid + 256 * it;
        int row = i >> 5;
        int k4 = (i & 31) << 2;
        int gr = row0 + row;
        float4 v = make_float4(0.f, 0.f, 0.f, 0.f);
        if (gr < NNODES) v = *(const float4*)&x[gr * HC + k4];
        __nv_bfloat16 h0 = __float2bfloat16_rn(v.x);
        __nv_bfloat16 h1 = __float2bfloat16_rn(v.y);
        __nv_bfloat16 h2 = __float2bfloat16_rn(v.z);
        __nv_bfloat16 h3 = __float2bfloat16_rn(v.w);
        __nv_bfloat16 l0 = __float2bfloat16_rn(v.x - __bfloat162float(h0));
        __nv_bfloat16 l1 = __float2bfloat16_rn(v.y - __bfloat162float(h1));
        __nv_bfloat16 l2 = __float2bfloat16_rn(v.z - __bfloat162float(h2));
        __nv_bfloat16 l3 = __float2bfloat16_rn(v.w - __bfloat162float(h3));
        uint32_t ph0 = (uint32_t)__bfloat16_as_ushort(h0) | ((uint32_t)__bfloat16_as_ushort(h1) << 16);
        uint32_t ph1 = (uint32_t)__bfloat16_as_ushort(h2) | ((uint32_t)__bfloat16_as_ushort(h3) << 16);
        uint32_t pl0 = (uint32_t)__bfloat16_as_ushort(l0) | ((uint32_t)__bfloat16_as_ushort(l1) << 16);
        uint32_t pl1 = (uint32_t)__bfloat16_as_ushort(l2) | ((uint32_t)__bfloat16_as_ushort(l3) << 16);
        int p = pk(k4);
        *(uint32_t*)&xsh[row * PIT + p] = ph0;
        *(uint32_t*)&xsh[row * PIT + p + 4] = ph1;
        *(uint32_t*)&xsl[row * PIT + p] = pl0;
        *(uint32_t*)&xsl[row * PIT + p + 4] = pl1;
    }
    __syncthreads();

    int w = tid >> 5, lane = tid & 31;
    int g = lane >> 2, t = lane & 3;
    int r0 = w * 16;

    float c[16][4];
    #pragma unroll
    for (int nt = 0; nt < 16; nt++)
        { c[nt][0] = 0.f; c[nt][1] = 0.f; c[nt][2] = 0.f; c[nt][3] = 0.f; }

    for (int k0 = 0; k0 < HC; k0 += 16) {
        int ab = k0 + 4 * t;
        uint2 ah0 = *(const uint2*)&xsh[(r0 + g) * PIT + ab];
        uint2 ah1 = *(const uint2*)&xsh[(r0 + g + 8) * PIT + ab];
        uint2 al0 = *(const uint2*)&xsl[(r0 + g) * PIT + ab];
        uint2 al1 = *(const uint2*)&xsl[(r0 + g + 8) * PIT + ab];
        #pragma unroll
        for (int nt = 0; nt < 16; nt++) {
            int n = nt * 8 + g;
            uint2 bh = *(const uint2*)&wsh[n * PIT + ab];
            uint2 bl = *(const uint2*)&wsl[n * PIT + ab];
            mma_bf16(c[nt], ah0.x, ah1.x, ah0.y, ah1.y, bh.x, bh.y);
            mma_bf16(c[nt], ah0.x, ah1.x, ah0.y, ah1.y, bl.x, bl.y);
            mma_bf16(c[nt], al0.x, al1.x, al0.y, al1.y, bh.x, bh.y);
        }
    }

    int gr0 = row0 + r0 + g;
    int gr1 = gr0 + 8;
    float as0[NHEADS], ad0[NHEADS], as1[NHEADS], ad1[NHEADS];
    #pragma unroll
    for (int hh = 0; hh < NHEADS; hh++)
        { as0[hh] = 0.f; ad0[hh] = 0.f; as1[hh] = 0.f; ad1[hh] = 0.f; }

    #pragma unroll
    for (int nt = 0; nt < 16; nt++) {
        int col = nt * 8 + t * 2;
        int hh = nt >> 1;
        float a0 = s_as[col], a1 = s_as[col + 1];
        float d0 = s_ad[col], d1 = s_ad[col + 1];
        as0[hh] += c[nt][0] * a0 + c[nt][1] * a1;
        ad0[hh] += c[nt][0] * d0 + c[nt][1] * d1;
        as1[hh] += c[nt][2] * a0 + c[nt][3] * a1;
        ad1[hh] += c[nt][2] * d0 + c[nt][3] * d1;
        if (gr0 < NNODES)
            *(float2*)&g_h[gr0 * HC + col] = make_float2(c[nt][0], c[nt][1]);
        if (gr1 < NNODES)
            *(float2*)&g_h[gr1 * HC + col] = make_float2(c[nt][2], c[nt][3]);
    }
    #pragma unroll
    for (int hh = 0; hh < NHEADS; hh++) {
        #pragma unroll
        for (int o = 1; o <= 2; o <<= 1) {
            as0[hh] += __shfl_xor_sync(0xffffffffu, as0[hh], o);
            ad0[hh] += __shfl_xor_sync(0xffffffffu, ad0[hh], o);
            as1[hh] += __shfl_xor_sync(0xffffffffu, as1[hh], o);
            ad1[hh] += __shfl_xor_sync(0xffffffffu, ad1[hh], o);
        }
    }
    if (t == 0) {
        #pragma unroll
        for (int hh = 0; hh < NHEADS; hh++) {
            if (gr0 < NNODES) {
                g_asrc[gr0 * NHEADS + hh] = as0[hh];
                g_adst[gr0 * NHEADS + hh] = ad0[hh];
            }
            if (gr1 < NNODES) {
                g_asrc[gr1 * NHEADS + hh] = as1[hh];
                g_adst[gr1 * NHEADS + hh] = ad1[hh];
            }
        }
    }
}

// ---------------- fused softmax + aggregate + residual + LN + ELU (R9 2-wide) --------
__global__ void k_agg(const float* __restrict__ x, const float* __restrict__ b,
                      const float* __restrict__ gamma, const float* __restrict__ beta,
                      float* __restrict__ out) {
    int gw = (blockIdx.x * blockDim.x + threadIdx.x) >> 5;
    if (gw >= NNODES) return;
    int n = gw;
    int lane = threadIdx.x & 31;
    int cb = lane * 4;
    int head = lane >> 2;

    int beg = g_rowstart[n];
    int end = g_rowstart[n + 1];
    float adst2 = g_adst[n * NHEADS + head] + g_coefB[head];
    float cA = g_coefA[head];

    float4 acc0 = make_float4(0.f, 0.f, 0.f, 0.f);
    float4 acc1 = make_float4(0.f, 0.f, 0.f, 0.f);
    float sum0 = 0.f, sum1 = 0.f;

    for (int base = beg; base < end; base += 32) {
        int i = base + lane;
        int sj = 0; float aj = 0.f;
        if (i < end) {
            long long p = g_edge[i];
            sj = (int)(unsigned)p;
            aj = __int_as_float((int)(p >> 32));
        }
        int m = end - base; if (m > 32) m = 32;
        int tt = 0;
        for (; tt + 1 < m; tt += 2) {
            int   s0 = __shfl_sync(0xffffffffu, sj, tt);
            int   s1 = __shfl_sync(0xffffffffu, sj, tt + 1);
            float a0 = __shfl_sync(0xffffffffu, aj, tt);
            float a1 = __shfl_sync(0xffffffffu, aj, tt + 1);
            float l0 = fmaf(a0, cA, g_asrc[s0 * NHEADS + head] + adst2);
            float l1 = fmaf(a1, cA, g_asrc[s1 * NHEADS + head] + adst2);
            l0 = l0 > 0.f ? l0 : NEG_SLOPE * l0;
            l1 = l1 > 0.f ? l1 : NEG_SLOPE * l1;
            float e0 = __expf(l0);
            float e1 = __expf(l1);
            float4 h0 = *(const float4*)&g_h[s0 * HC + cb];
            float4 h1 = *(const float4*)&g_h[s1 * HC + cb];
            sum0 += e0; sum1 += e1;
            acc0.x += e0 * h0.x; acc0.y += e0 * h0.y; acc0.z += e0 * h0.z; acc0.w += e0 * h0.w;
            acc1.x += e1 * h1.x; acc1.y += e1 * h1.y; acc1.z += e1 * h1.z; acc1.w += e1 * h1.w;
        }
        if (tt < m) {
            int   s0 = __shfl_sync(0xffffffffu, sj, tt);
            float a0 = __shfl_sync(0xffffffffu, aj, tt);
            float l0 = fmaf(a0, cA, g_asrc[s0 * NHEADS + head] + adst2);
            l0 = l0 > 0.f ? l0 : NEG_SLOPE * l0;
            float e0 = __expf(l0);
            float4 h0 = *(const float4*)&g_h[s0 * HC + cb];
            sum0 += e0;
            acc0.x += e0 * h0.x; acc0.y += e0 * h0.y; acc0.z += e0 * h0.z; acc0.w += e0 * h0.w;
        }
    }
    float sum = sum0 + sum1;
    float4 acc = make_float4(acc0.x + acc1.x, acc0.y + acc1.y, acc0.z + acc1.z, acc0.w + acc1.w);

    float inv = 1.f / (sum + 1e-16f);
    float4 xv = *(const float4*)&x[n * HC + cb];
    float4 bv = *(const float4*)&b[cb];
    float4 o;
    o.x = acc.x * inv + bv.x + xv.x;
    o.y = acc.y * inv + bv.y + xv.y;
    o.z = acc.z * inv + bv.z + xv.z;
    o.w = acc.w * inv + bv.w + xv.w;

    float s1 = o.x + o.y + o.z + o.w;
    float s2 = o.x * o.x + o.y * o.y + o.z * o.z + o.w * o.w;
    #pragma unroll
    for (int off = 16; off >= 1; off >>= 1) {
        s1 += __shfl_xor_sync(0xffffffffu, s1, off);
        s2 += __shfl_xor_sync(0xffffffffu, s2, off);
    }
    float mu = s1 * (1.f / 128.f);
    float var = s2 * (1.f / 128.f) - mu * mu;
    float rstd = rsqrtf(var + LN_EPS);
    float4 g4 = *(const float4*)&gamma[cb];
    float4 be4 = *(const float4*)&beta[cb];
    o.x = (o.x - mu) * rstd * g4.x + be4.x;
    o.y = (o.y - mu) * rstd * g4.y + be4.y;
    o.z = (o.z - mu) * rstd * g4.z + be4.z;
    o.w = (o.w - mu) * rstd * g4.w + be4.w;
    o.x = o.x > 0.f ? o.x : expm1f(o.x);
    o.y = o.y > 0.f ? o.y : expm1f(o.y);
    o.z = o.z > 0.f ? o.z : expm1f(o.z);
    o.w = o.w > 0.f ? o.w : expm1f(o.w);

    *(float4*)&out[n * HC + cb] = o;
}

// ---------------- launch ----------------
extern "C" void kernel_launch(void* const* d_in, const int* in_sizes, int n_in,
                              void* d_out, int out_size) {
    const float* x        = (const float*)d_in[0];
    const int*   ei       = (const int*)d_in[1];
    const float* ea       = (const float*)d_in[2];
    const float* W        = (const float*)d_in[3];
    const float* b        = (const float*)d_in[4];
    const float* att_src  = (const float*)d_in[5];
    const float* att_dst  = (const float*)d_in[6];
    const float* att_edge = (const float*)d_in[7];
    const float* lw       = (const float*)d_in[8];
    const float* lb       = (const float*)d_in[9];
    const float* gamma    = (const float*)d_in[10];
    const float* beta     = (const float*)d_in[11];
    const int* src = ei;
    const int* dst = ei + NEDGES;
    float* out = (float*)d_out;

    const int smem_sz = 4 * HC * PIT * (int)sizeof(uint16_t) + 2 * HC * (int)sizeof(float);
    cudaFuncSetAttribute(k_gemm_mma, cudaFuncAttributeMaxDynamicSharedMemorySize, smem_sz);

    k_prep<<<65 + ZERO_NBLK, 256>>>(W, lw, lb, att_edge);
    k_count<<<(NEDGES + 255) / 256, 256>>>(dst);
    k_gemm_mma<<<GEMM_NBLK, 256, smem_sz>>>(x, att_src, att_dst);
    k_scanA<<<SCAN_NBLK, 1024>>>();
    k_scanB<<<1, 64>>>();
    k_scanC<<<SCAN_NBLK, 1024>>>();
    k_scatter<<<(NEDGES + 255) / 256, 256>>>(src, dst, ea);
    k_agg<<<(NNODES * 32 + 255) / 256, 256>>>(x, b, gamma, beta, out);
}

// round 12
// speedup vs baseline: 1.1354x; 1.0072x over previous
#include <cuda_runtime.h>
#include <cuda_bf16.h>
#include <math.h>
#include <stdint.h>

#define NNODES 50000
#define NEDGES 800000
#define HC 128
#define NHEADS 8
#define NEG_SLOPE 0.2f
#define LN_EPS 1e-5f
#define SCAN_NBLK ((NNODES + 1023) / 1024)
#define GEMM_TM 128
#define GEMM_NBLK ((NNODES + GEMM_TM - 1) / GEMM_TM)
#define PIT 132
#define ZERO_NBLK ((NNODES + 1 + 255) / 256)

// ---------------- scratch ----------------
__device__ float g_h[NNODES * HC];
__device__ float g_asrc[NNODES * NHEADS];
__device__ float g_adst[NNODES * NHEADS];
__device__ float g_coefA[NHEADS];
__device__ float g_coefB[NHEADS];
__device__ int   g_rowstart[NNODES + 1];
__device__ int   g_rank[NEDGES];          // per-edge rank among same-dst edges
__device__ long long g_edge[NEDGES];      // packed (eav<<32 | src), sorted by dst
__device__ int   g_bsum[SCAN_NBLK];
__device__ int   g_bsumscan[SCAN_NBLK];
__device__ __nv_bfloat16 g_Wh[HC * HC];
__device__ __nv_bfloat16 g_Wl[HC * HC];

// k-permutation for mma fragment loads
__host__ __device__ __forceinline__ int pk(int k) {
    int b = k & 15;
    return (k & ~15) + (((b & 7) >> 1) << 2) + (((b >> 3) & 1) << 1) + (b & 1);
}

__device__ __forceinline__ void mma_bf16(float c[4], uint32_t a0, uint32_t a1,
                                         uint32_t a2, uint32_t a3,
                                         uint32_t b0, uint32_t b1) {
    asm volatile(
        "mma.sync.aligned.m16n8k16.row.col.f32.bf16.bf16.f32 "
        "{%0,%1,%2,%3}, {%4,%5,%6,%7}, {%8,%9}, {%0,%1,%2,%3};"
        : "+f"(c[0]), "+f"(c[1]), "+f"(c[2]), "+f"(c[3])
        : "r"(a0), "r"(a1), "r"(a2), "r"(a3), "r"(b0), "r"(b1));
}

// ---------------- fused prep: W split/permute + coef + rowstart zero ----------------
__global__ void k_prep(const float* __restrict__ W, const float* __restrict__ lw,
                       const float* __restrict__ lb, const float* __restrict__ ae) {
    int bx = blockIdx.x, t = threadIdx.x;
    if (bx < 64) {                         // W: 16384 elems
        int i = bx * 256 + t;
        int k = i >> 7, n = i & 127;
        float w = W[i];
        __nv_bfloat16 hi = __float2bfloat16_rn(w);
        __nv_bfloat16 lo = __float2bfloat16_rn(w - __bfloat162float(hi));
        int off = n * HC + pk(k);
        g_Wh[off] = hi;
        g_Wl[off] = lo;
    } else if (bx == 64) {                 // edge-MLP collapse
        if (t < 128) {
            int h = t >> 4, c = t & 15;
            float a  = ae[t];
            float pA = lw[t] * a;
            float pB = lb[t] * a;
            #pragma unroll
            for (int o = 8; o >= 1; o >>= 1) {
                pA += __shfl_xor_sync(0xffffffffu, pA, o);
                pB += __shfl_xor_sync(0xffffffffu, pB, o);
            }
            if (c == 0) { g_coefA[h] = pA; g_coefB[h] = pB; }
        }
    } else {                               // zero rowstart
        int i = (bx - 65) * 256 + t;
        if (i <= NNODES) g_rowstart[i] = 0;
    }
}

// ---------------- CSR build ----------------
// count + record per-edge rank (the atomic's return value)
__global__ void k_count(const int* __restrict__ dst) {
    int e = blockIdx.x * blockDim.x + threadIdx.x;
    if (e < NEDGES) {
        int r = atomicAdd(&g_rowstart[dst[e] + 1], 1);
        g_rank[e] = r;
    }
}
__global__ void k_scanA() {
    __shared__ int ws[32];
    int t = threadIdx.x, lane = t & 31, w = t >> 5;
    int idx = 1 + blockIdx.x * 1024 + t;
    int v = (idx <= NNODES) ? g_rowstart[idx] : 0;
    int xv = v;
    #pragma unroll
    for (int o = 1; o < 32; o <<= 1) {
        int y = __shfl_up_sync(0xffffffffu, xv, o);
        if (lane >= o) xv += y;
    }
    if (lane == 31) ws[w] = xv;
    __syncthreads();
    if (w == 0) {
        int s = ws[lane];
        #pragma unroll
        for (int o = 1; o < 32; o <<= 1) {
            int y = __shfl_up_sync(0xffffffffu, s, o);
            if (lane >= o) s += y;
        }
        ws[lane] = s;
    }
    __syncthreads();
    int incl = xv + (w > 0 ? ws[w - 1] : 0);
    if (idx <= NNODES) g_rowstart[idx] = incl;
    if (t == 1023) g_bsum[blockIdx.x] = incl;
}
__global__ void k_scanB() {
    __shared__ int ws[2];
    int t = threadIdx.x, lane = t & 31, w = t >> 5;
    int v = (t < SCAN_NBLK) ? g_bsum[t] : 0;
    #pragma unroll
    for (int o = 1; o < 32; o <<= 1) {
        int y = __shfl_up_sync(0xffffffffu, v, o);
        if (lane >= o) v += y;
    }
    if (lane == 31) ws[w] = v;
    __syncthreads();
    if (w == 1) v += ws[0];
    if (t < SCAN_NBLK) g_bsumscan[t] = v;
}
__global__ void k_scanC() {
    int t = threadIdx.x;
    int idx = 1 + blockIdx.x * 1024 + t;
    if (blockIdx.x == 0 && t == 0) g_rowstart[0] = 0;
    if (idx <= NNODES) {
        int off = (blockIdx.x > 0) ? g_bsumscan[blockIdx.x - 1] : 0;
        g_rowstart[idx] = g_rowstart[idx] + off;
    }
}
// atomic-free scatter: pos = rowstart[d] + rank[e]
__global__ void k_scatter(const int* __restrict__ src, const int* __restrict__ dst,
                          const float* __restrict__ ea) {
    int e = blockIdx.x * blockDim.x + threadIdx.x;
    if (e < NEDGES) {
        int d = dst[e];
        int pos = g_rowstart[d] + g_rank[e];
        long long p = ((long long)__float_as_int(ea[e]) << 32) | (unsigned)src[e];
        g_edge[pos] = p;
    }
}

// ---------------- mma.sync GEMM (validated R9) ----------------
__global__ __launch_bounds__(256)
void k_gemm_mma(const float* __restrict__ x, const float* __restrict__ att_src,
                const float* __restrict__ att_dst) {
    extern __shared__ char sm[];
    uint16_t* xsh = (uint16_t*)sm;
    uint16_t* xsl = xsh + HC * PIT;
    uint16_t* wsh = xsl + HC * PIT;
    uint16_t* wsl = wsh + HC * PIT;
    float* s_as = (float*)(wsl + HC * PIT);
    float* s_ad = s_as + HC;

    int tid = threadIdx.x;
    int row0 = blockIdx.x * GEMM_TM;

    if (tid < HC) { s_as[tid] = att_src[tid]; s_ad[tid] = att_dst[tid]; }

    {
        const uint32_t* sh = (const uint32_t*)g_Wh;
        const uint32_t* sl = (const uint32_t*)g_Wl;
        #pragma unroll
        for (int jj = 0; jj < 32; jj++) {
            int j = tid + 256 * jj;
            int n = j >> 6, e2 = j & 63;
            *(uint32_t*)&wsh[n * PIT + e2 * 2] = sh[j];
            *(uint32_t*)&wsl[n * PIT + e2 * 2] = sl[j];
        }
    }

    #pragma unroll
    for (int it = 0; it < 16; it++) {
        int i = tid + 256 * it;
        int row = i >> 5;
        int k4 = (i & 31) << 2;
        int gr = row0 + row;
        float4 v = make_float4(0.f, 0.f, 0.f, 0.f);
        if (gr < NNODES) v = *(const float4*)&x[gr * HC + k4];
        __nv_bfloat16 h0 = __float2bfloat16_rn(v.x);
        __nv_bfloat16 h1 = __float2bfloat16_rn(v.y);
        __nv_bfloat16 h2 = __float2bfloat16_rn(v.z);
        __nv_bfloat16 h3 = __float2bfloat16_rn(v.w);
        __nv_bfloat16 l0 = __float2bfloat16_rn(v.x - __bfloat162float(h0));
        __nv_bfloat16 l1 = __float2bfloat16_rn(v.y - __bfloat162float(h1));
        __nv_bfloat16 l2 = __float2bfloat16_rn(v.z - __bfloat162float(h2));
        __nv_bfloat16 l3 = __float2bfloat16_rn(v.w - __bfloat162float(h3));
        uint32_t ph0 = (uint32_t)__bfloat16_as_ushort(h0) | ((uint32_t)__bfloat16_as_ushort(h1) << 16);
        uint32_t ph1 = (uint32_t)__bfloat16_as_ushort(h2) | ((uint32_t)__bfloat16_as_ushort(h3) << 16);
        uint32_t pl0 = (uint32_t)__bfloat16_as_ushort(l0) | ((uint32_t)__bfloat16_as_ushort(l1) << 16);
        uint32_t pl1 = (uint32_t)__bfloat16_as_ushort(l2) | ((uint32_t)__bfloat16_as_ushort(l3) << 16);
        int p = pk(k4);
        *(uint32_t*)&xsh[row * PIT + p] = ph0;
        *(uint32_t*)&xsh[row * PIT + p + 4] = ph1;
        *(uint32_t*)&xsl[row * PIT + p] = pl0;
        *(uint32_t*)&xsl[row * PIT + p + 4] = pl1;
    }
    __syncthreads();

    int w = tid >> 5, lane = tid & 31;
    int g = lane >> 2, t = lane & 3;
    int r0 = w * 16;

    float c[16][4];
    #pragma unroll
    for (int nt = 0; nt < 16; nt++)
        { c[nt][0] = 0.f; c[nt][1] = 0.f; c[nt][2] = 0.f; c[nt][3] = 0.f; }

    for (int k0 = 0; k0 < HC; k0 += 16) {
        int ab = k0 + 4 * t;
        uint2 ah0 = *(const uint2*)&xsh[(r0 + g) * PIT + ab];
        uint2 ah1 = *(const uint2*)&xsh[(r0 + g + 8) * PIT + ab];
        uint2 al0 = *(const uint2*)&xsl[(r0 + g) * PIT + ab];
        uint2 al1 = *(const uint2*)&xsl[(r0 + g + 8) * PIT + ab];
        #pragma unroll
        for (int nt = 0; nt < 16; nt++) {
            int n = nt * 8 + g;
            uint2 bh = *(const uint2*)&wsh[n * PIT + ab];
            uint2 bl = *(const uint2*)&wsl[n * PIT + ab];
            mma_bf16(c[nt], ah0.x, ah1.x, ah0.y, ah1.y, bh.x, bh.y);
            mma_bf16(c[nt], ah0.x, ah1.x, ah0.y, ah1.y, bl.x, bl.y);
            mma_bf16(c[nt], al0.x, al1.x, al0.y, al1.y, bh.x, bh.y);
        }
    }

    int gr0 = row0 + r0 + g;
    int gr1 = gr0 + 8;
    float as0[NHEADS], ad0[NHEADS], as1[NHEADS], ad1[NHEADS];
    #pragma unroll
    for (int hh = 0; hh < NHEADS; hh++)
        { as0[hh] = 0.f; ad0[hh] = 0.f; as1[hh] = 0.f; ad1[hh] = 0.f; }

    #pragma unroll
    for (int nt = 0; nt < 16; nt++) {
        int col = nt * 8 + t * 2;
        int hh = nt >> 1;
        float a0 = s_as[col], a1 = s_as[col + 1];
        float d0 = s_ad[col], d1 = s_ad[col + 1];
        as0[hh] += c[nt][0] * a0 + c[nt][1] * a1;
        ad0[hh] += c[nt][0] * d0 + c[nt][1] * d1;
        as1[hh] += c[nt][2] * a0 + c[nt][3] * a1;
        ad1[hh] += c[nt][2] * d0 + c[nt][3] * d1;
        if (gr0 < NNODES)
            *(float2*)&g_h[gr0 * HC + col] = make_float2(c[nt][0], c[nt][1]);
        if (gr1 < NNODES)
            *(float2*)&g_h[gr1 * HC + col] = make_float2(c[nt][2], c[nt][3]);
    }
    #pragma unroll
    for (int hh = 0; hh < NHEADS; hh++) {
        #pragma unroll
        for (int o = 1; o <= 2; o <<= 1) {
            as0[hh] += __shfl_xor_sync(0xffffffffu, as0[hh], o);
            ad0[hh] += __shfl_xor_sync(0xffffffffu, ad0[hh], o);
            as1[hh] += __shfl_xor_sync(0xffffffffu, as1[hh], o);
            ad1[hh] += __shfl_xor_sync(0xffffffffu, ad1[hh], o);
        }
    }
    if (t == 0) {
        #pragma unroll
        for (int hh = 0; hh < NHEADS; hh++) {
            if (gr0 < NNODES) {
                g_asrc[gr0 * NHEADS + hh] = as0[hh];
                g_adst[gr0 * NHEADS + hh] = ad0[hh];
            }
            if (gr1 < NNODES) {
                g_asrc[gr1 * NHEADS + hh] = as1[hh];
                g_adst[gr1 * NHEADS + hh] = ad1[hh];
            }
        }
    }
}

// ---------------- fused softmax + aggregate + residual + LN + ELU ----------------
__global__ void k_agg(const float* __restrict__ x, const float* __restrict__ b,
                      const float* __restrict__ gamma, const float* __restrict__ beta,
                      float* __restrict__ out) {
    int gw = (blockIdx.x * blockDim.x + threadIdx.x) >> 5;
    if (gw >= NNODES) return;
    int n = gw;
    int lane = threadIdx.x & 31;
    int cb = lane * 4;
    int head = lane >> 2;

    int beg = g_rowstart[n];
    int end = g_rowstart[n + 1];
    float adst2 = g_adst[n * NHEADS + head] + g_coefB[head];
    float cA = g_coefA[head];

    float4 acc0 = make_float4(0.f, 0.f, 0.f, 0.f);
    float4 acc1 = make_float4(0.f, 0.f, 0.f, 0.f);
    float sum0 = 0.f, sum1 = 0.f;

    for (int base = beg; base < end; base += 32) {
        int i = base + lane;
        int sj = 0; float aj = 0.f;
        if (i < end) {
            long long p = g_edge[i];
            sj = (int)(unsigned)p;
            aj = __int_as_float((int)(p >> 32));
        }
        int m = end - base; if (m > 32) m = 32;
        int tt = 0;
        for (; tt + 1 < m; tt += 2) {
            int   s0 = __shfl_sync(0xffffffffu, sj, tt);
            int   s1 = __shfl_sync(0xffffffffu, sj, tt + 1);
            float a0 = __shfl_sync(0xffffffffu, aj, tt);
            float a1 = __shfl_sync(0xffffffffu, aj, tt + 1);
            float l0 = fmaf(a0, cA, g_asrc[s0 * NHEADS + head] + adst2);
            float l1 = fmaf(a1, cA, g_asrc[s1 * NHEADS + head] + adst2);
            l0 = l0 > 0.f ? l0 : NEG_SLOPE * l0;
            l1 = l1 > 0.f ? l1 : NEG_SLOPE * l1;
            float e0 = __expf(l0);
            float e1 = __expf(l1);
            float4 h0 = *(const float4*)&g_h[s0 * HC + cb];
            float4 h1 = *(const float4*)&g_h[s1 * HC + cb];
            sum0 += e0; sum1 += e1;
            acc0.x += e0 * h0.x; acc0.y += e0 * h0.y; acc0.z += e0 * h0.z; acc0.w += e0 * h0.w;
            acc1.x += e1 * h1.x; acc1.y += e1 * h1.y; acc1.z += e1 * h1.z; acc1.w += e1 * h1.w;
        }
        if (tt < m) {
            int   s0 = __shfl_sync(0xffffffffu, sj, tt);
            float a0 = __shfl_sync(0xffffffffu, aj, tt);
            float l0 = fmaf(a0, cA, g_asrc[s0 * NHEADS + head] + adst2);
            l0 = l0 > 0.f ? l0 : NEG_SLOPE * l0;
            float e0 = __expf(l0);
            float4 h0 = *(const float4*)&g_h[s0 * HC + cb];
            sum0 += e0;
            acc0.x += e0 * h0.x; acc0.y += e0 * h0.y; acc0.z += e0 * h0.z; acc0.w += e0 * h0.w;
        }
    }
    float sum = sum0 + sum1;
    float4 acc = make_float4(acc0.x + acc1.x, acc0.y + acc1.y, acc0.z + acc1.z, acc0.w + acc1.w);

    float inv = 1.f / (sum + 1e-16f);
    float4 xv = *(const float4*)&x[n * HC + cb];
    float4 bv = *(const float4*)&b[cb];
    float4 o;
    o.x = acc.x * inv + bv.x + xv.x;
    o.y = acc.y * inv + bv.y + xv.y;
    o.z = acc.z * inv + bv.z + xv.z;
    o.w = acc.w * inv + bv.w + xv.w;

    float s1 = o.x + o.y + o.z + o.w;
    float s2 = o.x * o.x + o.y * o.y + o.z * o.z + o.w * o.w;
    #pragma unroll
    for (int off = 16; off >= 1; off >>= 1) {
        s1 += __shfl_xor_sync(0xffffffffu, s1, off);
        s2 += __shfl_xor_sync(0xffffffffu, s2, off);
    }
    float mu = s1 * (1.f / 128.f);
    float var = s2 * (1.f / 128.f) - mu * mu;
    float rstd = rsqrtf(var + LN_EPS);
    float4 g4 = *(const float4*)&gamma[cb];
    float4 be4 = *(const float4*)&beta[cb];
    o.x = (o.x - mu) * rstd * g4.x + be4.x;
    o.y = (o.y - mu) * rstd * g4.y + be4.y;
    o.z = (o.z - mu) * rstd * g4.z + be4.z;
    o.w = (o.w - mu) * rstd * g4.w + be4.w;
    o.x = o.x > 0.f ? o.x : expm1f(o.x);
    o.y = o.y > 0.f ? o.y : expm1f(o.y);
    o.z = o.z > 0.f ? o.z : expm1f(o.z);
    o.w = o.w > 0.f ? o.w : expm1f(o.w);

    *(float4*)&out[n * HC + cb] = o;
}

// ---------------- launch ----------------
extern "C" void kernel_launch(void* const* d_in, const int* in_sizes, int n_in,
                              void* d_out, int out_size) {
    const float* x        = (const float*)d_in[0];
    const int*   ei       = (const int*)d_in[1];
    const float* ea       = (const float*)d_in[2];
    const float* W        = (const float*)d_in[3];
    const float* b        = (const float*)d_in[4];
    const float* att_src  = (const float*)d_in[5];
    const float* att_dst  = (const float*)d_in[6];
    const float* att_edge = (const float*)d_in[7];
    const float* lw       = (const float*)d_in[8];
    const float* lb       = (const float*)d_in[9];
    const float* gamma    = (const float*)d_in[10];
    const float* beta     = (const float*)d_in[11];
    const int* src = ei;
    const int* dst = ei + NEDGES;
    float* out = (float*)d_out;

    const int smem_sz = 4 * HC * PIT * (int)sizeof(uint16_t) + 2 * HC * (int)sizeof(float);
    cudaFuncSetAttribute(k_gemm_mma, cudaFuncAttributeMaxDynamicSharedMemorySize, smem_sz);

    k_prep<<<65 + ZERO_NBLK, 256>>>(W, lw, lb, att_edge);
    k_count<<<(NEDGES + 255) / 256, 256>>>(dst);
    k_gemm_mma<<<GEMM_NBLK, 256, smem_sz>>>(x, att_src, att_dst);
    k_scanA<<<SCAN_NBLK, 1024>>>();
    k_scanB<<<1, 64>>>();
    k_scanC<<<SCAN_NBLK, 1024>>>();
    k_scatter<<<(NEDGES + 255) / 256, 256>>>(src, dst, ea);
    k_agg<<<(NNODES * 32 + 255) / 256, 256>>>(x, b, gamma, beta, out);
}

// round 15
// speedup vs baseline: 1.1629x; 1.0242x over previous
#include <cuda_runtime.h>
#include <cuda_bf16.h>
#include <math.h>
#include <stdint.h>

#define NNODES 50000
#define NEDGES 800000
#define HC 128
#define NHEADS 8
#define NEG_SLOPE 0.2f
#define LN_EPS 1e-5f
#define SCAN_NBLK ((NNODES + 1023) / 1024)
#define GEMM_TM 128
#define GEMM_NBLK ((NNODES + GEMM_TM - 1) / GEMM_TM)
#define CNT_NBLK 782
#define PIT 132
#define ZERO_NBLK ((NNODES + 1 + 255) / 256)

// ---------------- scratch ----------------
__device__ float g_h[NNODES * HC];
__device__ float g_asrc[NNODES * NHEADS];
__device__ float g_adst[NNODES * NHEADS];
__device__ float g_coefA[NHEADS];
__device__ float g_coefB[NHEADS];
__device__ int   g_rowstart[NNODES + 1];  // raw per-chunk inclusive scan (final = +bsumscan)
__device__ int   g_rank[NEDGES];
__device__ long long g_edge[NEDGES];
__device__ int   g_bsum[SCAN_NBLK];
__device__ int   g_bsumscan[SCAN_NBLK];
__device__ int   g_ctr;
__device__ __nv_bfloat16 g_Wh[HC * HC];
__device__ __nv_bfloat16 g_Wl[HC * HC];

__host__ __device__ __forceinline__ int pk(int k) {
    int b = k & 15;
    return (k & ~15) + (((b & 7) >> 1) << 2) + (((b >> 3) & 1) << 1) + (b & 1);
}

__device__ __forceinline__ void mma_bf16(float c[4], uint32_t a0, uint32_t a1,
                                         uint32_t a2, uint32_t a3,
                                         uint32_t b0, uint32_t b1) {
    asm volatile(
        "mma.sync.aligned.m16n8k16.row.col.f32.bf16.bf16.f32 "
        "{%0,%1,%2,%3}, {%4,%5,%6,%7}, {%8,%9}, {%0,%1,%2,%3};"
        : "+f"(c[0]), "+f"(c[1]), "+f"(c[2]), "+f"(c[3])
        : "r"(a0), "r"(a1), "r"(a2), "r"(a3), "r"(b0), "r"(b1));
}

// final CSR offset from raw chunk-scan + chunk offsets
__device__ __forceinline__ int final_row(int idx) {
    if (idx == 0) return 0;
    int bx = (idx - 1) >> 10;
    int off = (bx > 0) ? g_bsumscan[bx - 1] : 0;
    return g_rowstart[idx] + off;
}

// ---------------- prep: W split/permute + coef + rowstart zero + ctr reset ----------
__global__ void k_prep(const float* __restrict__ W, const float* __restrict__ lw,
                       const float* __restrict__ lb, const float* __restrict__ ae) {
    int bx = blockIdx.x, t = threadIdx.x;
    if (bx < 64) {
        int i = bx * 256 + t;
        int k = i >> 7, n = i & 127;
        float w = W[i];
        __nv_bfloat16 hi = __float2bfloat16_rn(w);
        __nv_bfloat16 lo = __float2bfloat16_rn(w - __bfloat162float(hi));
        int off = n * HC + pk(k);
        g_Wh[off] = hi;
        g_Wl[off] = lo;
    } else if (bx == 64) {
        if (t < 128) {
            int h = t >> 4, c = t & 15;
            float a  = ae[t];
            float pA = lw[t] * a;
            float pB = lb[t] * a;
            #pragma unroll
            for (int o = 8; o >= 1; o >>= 1) {
                pA += __shfl_xor_sync(0xffffffffu, pA, o);
                pB += __shfl_xor_sync(0xffffffffu, pB, o);
            }
            if (c == 0) { g_coefA[h] = pA; g_coefB[h] = pB; }
        }
        if (t == 128) g_ctr = 0;
    } else {
        int i = (bx - 65) * 256 + t;
        if (i <= NNODES) g_rowstart[i] = 0;
    }
}

// ---------------- MEGA: gemm (blocks < GEMM_NBLK) + count (rest) ----------------
__global__ __launch_bounds__(256)
void k_mega(const float* __restrict__ x, const float* __restrict__ att_src,
            const float* __restrict__ att_dst, const int* __restrict__ dst) {
    int tid = threadIdx.x;
    if (blockIdx.x >= GEMM_NBLK) {
        // ---- count role: histogram + per-edge rank ----
        int base = (blockIdx.x - GEMM_NBLK) * 256 + tid;
        for (int e = base; e < NEDGES; e += CNT_NBLK * 256) {
            int r = atomicAdd(&g_rowstart[dst[e] + 1], 1);
            g_rank[e] = r;
        }
        return;
    }
    // ---- gemm role (validated R9) ----
    extern __shared__ char sm[];
    uint16_t* xsh = (uint16_t*)sm;
    uint16_t* xsl = xsh + HC * PIT;
    uint16_t* wsh = xsl + HC * PIT;
    uint16_t* wsl = wsh + HC * PIT;
    float* s_as = (float*)(wsl + HC * PIT);
    float* s_ad = s_as + HC;

    int row0 = blockIdx.x * GEMM_TM;

    if (tid < HC) { s_as[tid] = att_src[tid]; s_ad[tid] = att_dst[tid]; }

    {
        const uint32_t* sh = (const uint32_t*)g_Wh;
        const uint32_t* sl = (const uint32_t*)g_Wl;
        #pragma unroll
        for (int jj = 0; jj < 32; jj++) {
            int j = tid + 256 * jj;
            int n = j >> 6, e2 = j & 63;
            *(uint32_t*)&wsh[n * PIT + e2 * 2] = sh[j];
            *(uint32_t*)&wsl[n * PIT + e2 * 2] = sl[j];
        }
    }

    #pragma unroll
    for (int it = 0; it < 16; it++) {
        int i = tid + 256 * it;
        int row = i >> 5;
        int k4 = (i & 31) << 2;
        int gr = row0 + row;
        float4 v = make_float4(0.f, 0.f, 0.f, 0.f);
        if (gr < NNODES) v = *(const float4*)&x[gr * HC + k4];
        __nv_bfloat16 h0 = __float2bfloat16_rn(v.x);
        __nv_bfloat16 h1 = __float2bfloat16_rn(v.y);
        __nv_bfloat16 h2 = __float2bfloat16_rn(v.z);
        __nv_bfloat16 h3 = __float2bfloat16_rn(v.w);
        __nv_bfloat16 l0 = __float2bfloat16_rn(v.x - __bfloat162float(h0));
        __nv_bfloat16 l1 = __float2bfloat16_rn(v.y - __bfloat162float(h1));
        __nv_bfloat16 l2 = __float2bfloat16_rn(v.z - __bfloat162float(h2));
        __nv_bfloat16 l3 = __float2bfloat16_rn(v.w - __bfloat162float(h3));
        uint32_t ph0 = (uint32_t)__bfloat16_as_ushort(h0) | ((uint32_t)__bfloat16_as_ushort(h1) << 16);
        uint32_t ph1 = (uint32_t)__bfloat16_as_ushort(h2) | ((uint32_t)__bfloat16_as_ushort(h3) << 16);
        uint32_t pl0 = (uint32_t)__bfloat16_as_ushort(l0) | ((uint32_t)__bfloat16_as_ushort(l1) << 16);
        uint32_t pl1 = (uint32_t)__bfloat16_as_ushort(l2) | ((uint32_t)__bfloat16_as_ushort(l3) << 16);
        int p = pk(k4);
        *(uint32_t*)&xsh[row * PIT + p] = ph0;
        *(uint32_t*)&xsh[row * PIT + p + 4] = ph1;
        *(uint32_t*)&xsl[row * PIT + p] = pl0;
        *(uint32_t*)&xsl[row * PIT + p + 4] = pl1;
    }
    __syncthreads();

    int w = tid >> 5, lane = tid & 31;
    int g = lane >> 2, t = lane & 3;
    int r0 = w * 16;

    float c[16][4];
    #pragma unroll
    for (int nt = 0; nt < 16; nt++)
        { c[nt][0] = 0.f; c[nt][1] = 0.f; c[nt][2] = 0.f; c[nt][3] = 0.f; }

    for (int k0 = 0; k0 < HC; k0 += 16) {
        int ab = k0 + 4 * t;
        uint2 ah0 = *(const uint2*)&xsh[(r0 + g) * PIT + ab];
        uint2 ah1 = *(const uint2*)&xsh[(r0 + g + 8) * PIT + ab];
        uint2 al0 = *(const uint2*)&xsl[(r0 + g) * PIT + ab];
        uint2 al1 = *(const uint2*)&xsl[(r0 + g + 8) * PIT + ab];
        #pragma unroll
        for (int nt = 0; nt < 16; nt++) {
            int n = nt * 8 + g;
            uint2 bh = *(const uint2*)&wsh[n * PIT + ab];
            uint2 bl = *(const uint2*)&wsl[n * PIT + ab];
            mma_bf16(c[nt], ah0.x, ah1.x, ah0.y, ah1.y, bh.x, bh.y);
            mma_bf16(c[nt], ah0.x, ah1.x, ah0.y, ah1.y, bl.x, bl.y);
            mma_bf16(c[nt], al0.x, al1.x, al0.y, al1.y, bh.x, bh.y);
        }
    }

    int gr0 = row0 + r0 + g;
    int gr1 = gr0 + 8;
    float as0[NHEADS], ad0[NHEADS], as1[NHEADS], ad1[NHEADS];
    #pragma unroll
    for (int hh = 0; hh < NHEADS; hh++)
        { as0[hh] = 0.f; ad0[hh] = 0.f; as1[hh] = 0.f; ad1[hh] = 0.f; }

    #pragma unroll
    for (int nt = 0; nt < 16; nt++) {
        int col = nt * 8 + t * 2;
        int hh = nt >> 1;
        float a0 = s_as[col], a1 = s_as[col + 1];
        float d0 = s_ad[col], d1 = s_ad[col + 1];
        as0[hh] += c[nt][0] * a0 + c[nt][1] * a1;
        ad0[hh] += c[nt][0] * d0 + c[nt][1] * d1;
        as1[hh] += c[nt][2] * a0 + c[nt][3] * a1;
        ad1[hh] += c[nt][2] * d0 + c[nt][3] * d1;
        if (gr0 < NNODES)
            *(float2*)&g_h[gr0 * HC + col] = make_float2(c[nt][0], c[nt][1]);
        if (gr1 < NNODES)
            *(float2*)&g_h[gr1 * HC + col] = make_float2(c[nt][2], c[nt][3]);
    }
    #pragma unroll
    for (int hh = 0; hh < NHEADS; hh++) {
        #pragma unroll
        for (int o = 1; o <= 2; o <<= 1) {
            as0[hh] += __shfl_xor_sync(0xffffffffu, as0[hh], o);
            ad0[hh] += __shfl_xor_sync(0xffffffffu, ad0[hh], o);
            as1[hh] += __shfl_xor_sync(0xffffffffu, as1[hh], o);
            ad1[hh] += __shfl_xor_sync(0xffffffffu, ad1[hh], o);
        }
    }
    if (t == 0) {
        #pragma unroll
        for (int hh = 0; hh < NHEADS; hh++) {
            if (gr0 < NNODES) {
                g_asrc[gr0 * NHEADS + hh] = as0[hh];
                g_adst[gr0 * NHEADS + hh] = ad0[hh];
            }
            if (gr1 < NNODES) {
                g_asrc[gr1 * NHEADS + hh] = as1[hh];
                g_adst[gr1 * NHEADS + hh] = ad1[hh];
            }
        }
    }
}

// ---------------- scanA with fused scanB (last-block pattern) ----------------
__global__ void k_scanAB() {
    __shared__ int ws[32];
    __shared__ int s_last;
    int t = threadIdx.x, lane = t & 31, w = t >> 5;
    int idx = 1 + blockIdx.x * 1024 + t;
    int v = (idx <= NNODES) ? g_rowstart[idx] : 0;
    int xv = v;
    #pragma unroll
    for (int o = 1; o < 32; o <<= 1) {
        int y = __shfl_up_sync(0xffffffffu, xv, o);
        if (lane >= o) xv += y;
    }
    if (lane == 31) ws[w] = xv;
    __syncthreads();
    if (w == 0) {
        int s = ws[lane];
        #pragma unroll
        for (int o = 1; o < 32; o <<= 1) {
            int y = __shfl_up_sync(0xffffffffu, s, o);
            if (lane >= o) s += y;
        }
        ws[lane] = s;
    }
    __syncthreads();
    int incl = xv + (w > 0 ? ws[w - 1] : 0);
    if (idx <= NNODES) g_rowstart[idx] = incl;
    if (t == 1023) g_bsum[blockIdx.x] = incl;
    // fused scanB: last finishing block scans the SCAN_NBLK partials
    __threadfence();
    __syncthreads();
    if (t == 0) s_last = (atomicAdd(&g_ctr, 1) == SCAN_NBLK - 1) ? 1 : 0;
    __syncthreads();
    if (s_last) {
        __threadfence();                    // acquire other blocks' bsum writes
        if (t < 64) {
            int bv = (t < SCAN_NBLK) ? g_bsum[t] : 0;
            #pragma unroll
            for (int o = 1; o < 32; o <<= 1) {
                int y = __shfl_up_sync(0xffffffffu, bv, o);
                if (lane >= o) bv += y;
            }
            if (lane == 31) ws[16 + w] = bv;   // stash warp totals
            __syncwarp();
        }
        __syncthreads();
        if (t < 64) {
            int bv = (t < SCAN_NBLK) ? g_bsum[t] : 0;
            #pragma unroll
            for (int o = 1; o < 32; o <<= 1) {
                int y = __shfl_up_sync(0xffffffffu, bv, o);
                if (lane >= o) bv += y;
            }
            if (t >= 32) bv += ws[16];
            if (t < SCAN_NBLK) g_bsumscan[t] = bv;
        }
    }
}

// ---------------- scatter (atomic-free, on-the-fly offsets) ----------------
__global__ void k_scatter(const int* __restrict__ src, const int* __restrict__ dst,
                          const float* __restrict__ ea) {
    int e = blockIdx.x * blockDim.x + threadIdx.x;
    if (e < NEDGES) {
        int d = dst[e];
        int pos = final_row(d) + g_rank[e];
        long long p = ((long long)__float_as_int(ea[e]) << 32) | (unsigned)src[e];
        g_edge[pos] = p;
    }
}

// ---------------- fused softmax + aggregate + residual + LN + ELU ----------------
__global__ void k_agg(const float* __restrict__ x, const float* __restrict__ b,
                      const float* __restrict__ gamma, const float* __restrict__ beta,
                      float* __restrict__ out) {
    int gw = (blockIdx.x * blockDim.x + threadIdx.x) >> 5;
    if (gw >= NNODES) return;
    int n = gw;
    int lane = threadIdx.x & 31;
    int cb = lane * 4;
    int head = lane >> 2;

    int beg = final_row(n);
    int end = final_row(n + 1);
    float adst2 = g_adst[n * NHEADS + head] + g_coefB[head];
    float cA = g_coefA[head];

    float4 acc0 = make_float4(0.f, 0.f, 0.f, 0.f);
    float4 acc1 = make_float4(0.f, 0.f, 0.f, 0.f);
    float sum0 = 0.f, sum1 = 0.f;

    for (int base = beg; base < end; base += 32) {
        int i = base + lane;
        int sj = 0; float aj = 0.f;
        if (i < end) {
            long long p = g_edge[i];
            sj = (int)(unsigned)p;
            aj = __int_as_float((int)(p >> 32));
        }
        int m = end - base; if (m > 32) m = 32;
        int tt = 0;
        for (; tt + 1 < m; tt += 2) {
            int   s0 = __shfl_sync(0xffffffffu, sj, tt);
            int   s1 = __shfl_sync(0xffffffffu, sj, tt + 1);
            float a0 = __shfl_sync(0xffffffffu, aj, tt);
            float a1 = __shfl_sync(0xffffffffu, aj, tt + 1);
            float l0 = fmaf(a0, cA, g_asrc[s0 * NHEADS + head] + adst2);
            float l1 = fmaf(a1, cA, g_asrc[s1 * NHEADS + head] + adst2);
            l0 = l0 > 0.f ? l0 : NEG_SLOPE * l0;
            l1 = l1 > 0.f ? l1 : NEG_SLOPE * l1;
            float e0 = __expf(l0);
            float e1 = __expf(l1);
            float4 h0 = *(const float4*)&g_h[s0 * HC + cb];
            float4 h1 = *(const float4*)&g_h[s1 * HC + cb];
            sum0 += e0; sum1 += e1;
            acc0.x += e0 * h0.x; acc0.y += e0 * h0.y; acc0.z += e0 * h0.z; acc0.w += e0 * h0.w;
            acc1.x += e1 * h1.x; acc1.y += e1 * h1.y; acc1.z += e1 * h1.z; acc1.w += e1 * h1.w;
        }
        if (tt < m) {
            int   s0 = __shfl_sync(0xffffffffu, sj, tt);
            float a0 = __shfl_sync(0xffffffffu, aj, tt);
            float l0 = fmaf(a0, cA, g_asrc[s0 * NHEADS + head] + adst2);
            l0 = l0 > 0.f ? l0 : NEG_SLOPE * l0;
            float e0 = __expf(l0);
            float4 h0 = *(const float4*)&g_h[s0 * HC + cb];
            sum0 += e0;
            acc0.x += e0 * h0.x; acc0.y += e0 * h0.y; acc0.z += e0 * h0.z; acc0.w += e0 * h0.w;
        }
    }
    float sum = sum0 + sum1;
    float4 acc = make_float4(acc0.x + acc1.x, acc0.y + acc1.y, acc0.z + acc1.z, acc0.w + acc1.w);

    float inv = 1.f / (sum + 1e-16f);
    float4 xv = *(const float4*)&x[n * HC + cb];
    float4 bv = *(const float4*)&b[cb];
    float4 o;
    o.x = acc.x * inv + bv.x + xv.x;
    o.y = acc.y * inv + bv.y + xv.y;
    o.z = acc.z * inv + bv.z + xv.z;
    o.w = acc.w * inv + bv.w + xv.w;

    float s1 = o.x + o.y + o.z + o.w;
    float s2 = o.x * o.x + o.y * o.y + o.z * o.z + o.w * o.w;
    #pragma unroll
    for (int off = 16; off >= 1; off >>= 1) {
        s1 += __shfl_xor_sync(0xffffffffu, s1, off);
        s2 += __shfl_xor_sync(0xffffffffu, s2, off);
    }
    float mu = s1 * (1.f / 128.f);
    float var = s2 * (1.f / 128.f) - mu * mu;
    float rstd = rsqrtf(var + LN_EPS);
    float4 g4 = *(const float4*)&gamma[cb];
    float4 be4 = *(const float4*)&beta[cb];
    o.x = (o.x - mu) * rstd * g4.x + be4.x;
    o.y = (o.y - mu) * rstd * g4.y + be4.y;
    o.z = (o.z - mu) * rstd * g4.z + be4.z;
    o.w = (o.w - mu) * rstd * g4.w + be4.w;
    o.x = o.x > 0.f ? o.x : expm1f(o.x);
    o.y = o.y > 0.f ? o.y : expm1f(o.y);
    o.z = o.z > 0.f ? o.z : expm1f(o.z);
    o.w = o.w > 0.f ? o.w : expm1f(o.w);

    *(float4*)&out[n * HC + cb] = o;
}

// ---------------- launch ----------------
extern "C" void kernel_launch(void* const* d_in, const int* in_sizes, int n_in,
                              void* d_out, int out_size) {
    const float* x        = (const float*)d_in[0];
    const int*   ei       = (const int*)d_in[1];
    const float* ea       = (const float*)d_in[2];
    const float* W        = (const float*)d_in[3];
    const float* b        = (const float*)d_in[4];
    const float* att_src  = (const float*)d_in[5];
    const float* att_dst  = (const float*)d_in[6];
    const float* att_edge = (const float*)d_in[7];
    const float* lw       = (const float*)d_in[8];
    const float* lb       = (const float*)d_in[9];
    const float* gamma    = (const float*)d_in[10];
    const float* beta     = (const float*)d_in[11];
    const int* src = ei;
    const int* dst = ei + NEDGES;
    float* out = (float*)d_out;

    const int smem_sz = 4 * HC * PIT * (int)sizeof(uint16_t) + 2 * HC * (int)sizeof(float);
    cudaFuncSetAttribute(k_mega, cudaFuncAttributeMaxDynamicSharedMemorySize, smem_sz);

    k_prep<<<65 + ZERO_NBLK, 256>>>(W, lw, lb, att_edge);
    k_mega<<<GEMM_NBLK + CNT_NBLK, 256, smem_sz>>>(x, att_src, att_dst, dst);
    k_scanAB<<<SCAN_NBLK, 1024>>>();
    k_scatter<<<(NEDGES + 255) / 256, 256>>>(src, dst, ea);
    k_agg<<<(NNODES * 32 + 255) / 256, 256>>>(x, b, gamma, beta, out);
}